// round 1
// baseline (speedup 1.0000x reference)
#include <cuda_runtime.h>
#include <cuda_bf16.h>
#include <cstdint>

// Problem constants
#define B_SZ     2048
#define D_SZ     128
#define C_SZ     64
#define T_STEPS  300
#define H1       200      // embedding hidden
#define HU       100      // UMNN hidden (real)
#define HP       128      // UMNN hidden (padded)
#define ROWS_TOTAL (B_SZ * T_STEPS)       // 614400
#define CTA_ROWS 128
#define NUM_CTAS (ROWS_TOTAL / CTA_ROWS)  // 4800 (exact)

#define LDS_ROW  136      // bf16 elements per smem row (128 + 8 pad -> conflict-free ldmatrix)
#define SMEM_MAIN (3 * 128 * LDS_ROW * 2) // 104448 bytes

// ------------------------- device scratch (no allocation allowed) -------------------------
__device__ float g_h1[B_SZ * H1];
__device__ float g_h2[B_SZ * H1];
__device__ float g_h [B_SZ * C_SZ];
__device__ float g_P [B_SZ * HP];   // x @ U1[:128,:]  padded to 128 cols (zeros)
__device__ float g_Q [B_SZ * HP];   // h @ U1[128:,:] + c1, padded
__device__ __nv_bfloat16 g_U2b[HP * HP];
__device__ __nv_bfloat16 g_U3b[HP * HP];
__device__ __nv_bfloat16 g_U4b[HP * HP];
__device__ float g_c2p[HP], g_c3p[HP], g_c4p[HP];
__device__ float g_F[B_SZ];

// ------------------------- generic small SIMT GEMM (prep stages) -------------------------
// C[r][c] = act( sum_k A[r][k] * W[k][c] + bias[c] ), guards on M/N/K, zero-pads to Nstore.
__global__ void gemm_kernel(const float* __restrict__ A, int lda,
                            const float* __restrict__ W, int ldw,
                            const float* __restrict__ bias,
                            float* __restrict__ C, int ldc,
                            int M, int N, int K, int Nstore, int act)
{
    __shared__ float As[16][68];
    __shared__ float Ws[16][68];
    int tid = threadIdx.x;
    int tx = tid & 15, ty = tid >> 4;
    int m0 = blockIdx.y * 64, n0 = blockIdx.x * 64;
    float acc[4][4] = {};
    int ktiles = (K + 15) >> 4;
    for (int kt = 0; kt < ktiles; kt++) {
        int k0 = kt * 16;
        #pragma unroll
        for (int it = 0; it < 4; it++) {             // A tile 64x16 -> As[k][r]
            int e = tid + it * 256;
            int r = e >> 4, k = e & 15;
            float v = 0.f;
            if (m0 + r < M && k0 + k < K) v = A[(m0 + r) * lda + k0 + k];
            As[k][r] = v;
        }
        #pragma unroll
        for (int it = 0; it < 4; it++) {             // W tile 16x64 -> Ws[k][c]
            int e = tid + it * 256;
            int k = e >> 6, c = e & 63;
            float v = 0.f;
            if (k0 + k < K && n0 + c < N) v = W[(k0 + k) * ldw + n0 + c];
            Ws[k][c] = v;
        }
        __syncthreads();
        #pragma unroll
        for (int k = 0; k < 16; k++) {
            float4 a = *(const float4*)&As[k][ty * 4];
            float4 w = *(const float4*)&Ws[k][tx * 4];
            float av[4] = {a.x, a.y, a.z, a.w};
            float wv[4] = {w.x, w.y, w.z, w.w};
            #pragma unroll
            for (int i = 0; i < 4; i++)
                #pragma unroll
                for (int j = 0; j < 4; j++)
                    acc[i][j] += av[i] * wv[j];
        }
        __syncthreads();
    }
    #pragma unroll
    for (int i = 0; i < 4; i++) {
        int r = m0 + ty * 4 + i;
        if (r >= M) continue;
        #pragma unroll
        for (int j = 0; j < 4; j++) {
            int c = n0 + tx * 4 + j;
            if (c >= Nstore) continue;
            float v = 0.f;
            if (c < N) {
                v = acc[i][j] + (bias ? bias[c] : 0.f);
                if (act == 1) v = fmaxf(v, 0.f);
            }
            C[r * ldc + c] = v;
        }
    }
}

// ------------------------- pack weights to padded bf16 + biases + zero F -----------------
__global__ void pack_kernel(const float* __restrict__ U2, const float* __restrict__ U3,
                            const float* __restrict__ U4, const float* __restrict__ c2,
                            const float* __restrict__ c3, const float* __restrict__ c4)
{
    int e = blockIdx.x * blockDim.x + threadIdx.x;  // 0..16383
    int which = blockIdx.y;
    if (which < 3) {
        int k = e >> 7, n = e & 127;
        const float* src = which == 0 ? U2 : (which == 1 ? U3 : U4);
        int Kr = HU, Nr = (which == 2) ? D_SZ : HU;
        float v = (k < Kr && n < Nr) ? src[k * Nr + n] : 0.f;
        __nv_bfloat16* dst = which == 0 ? g_U2b : (which == 1 ? g_U3b : g_U4b);
        dst[k * HP + n] = __float2bfloat16(v);
    } else {
        if (e < HP) {
            g_c2p[e] = e < HU ? c2[e] : 0.f;
            g_c3p[e] = e < HU ? c3[e] : 0.f;
            g_c4p[e] = c4[e];
        }
        if (e < B_SZ) g_F[e] = 0.f;
    }
}

// ------------------------- mma.sync bf16 helpers -------------------------
__device__ __forceinline__ uint32_t smem_u32(const void* p) {
    return (uint32_t)__cvta_generic_to_shared(p);
}
__device__ __forceinline__ void ldm_x4(uint32_t addr, uint32_t& r0, uint32_t& r1,
                                       uint32_t& r2, uint32_t& r3) {
    asm volatile("ldmatrix.sync.aligned.m8n8.x4.shared.b16 {%0,%1,%2,%3}, [%4];"
                 : "=r"(r0), "=r"(r1), "=r"(r2), "=r"(r3) : "r"(addr));
}
__device__ __forceinline__ void ldm_x4_t(uint32_t addr, uint32_t& r0, uint32_t& r1,
                                         uint32_t& r2, uint32_t& r3) {
    asm volatile("ldmatrix.sync.aligned.m8n8.x4.trans.shared.b16 {%0,%1,%2,%3}, [%4];"
                 : "=r"(r0), "=r"(r1), "=r"(r2), "=r"(r3) : "r"(addr));
}
__device__ __forceinline__ void mma_bf16(float c[4], uint32_t a0, uint32_t a1, uint32_t a2,
                                         uint32_t a3, uint32_t b0, uint32_t b1) {
    asm volatile(
        "mma.sync.aligned.m16n8k16.row.col.f32.bf16.bf16.f32 "
        "{%0,%1,%2,%3},{%4,%5,%6,%7},{%8,%9},{%0,%1,%2,%3};"
        : "+f"(c[0]), "+f"(c[1]), "+f"(c[2]), "+f"(c[3])
        : "r"(a0), "r"(a1), "r"(a2), "r"(a3), "r"(b0), "r"(b1));
}

// Warp-tiled 128x128x128 GEMM from smem (A: [128][LDS_ROW] bf16 row-major,
// W: [k][n] bf16 row-major). Warp layout: 4 m-warps x 2 n-warps, warp tile 32x64.
__device__ __forceinline__ void gemm128(const __nv_bfloat16* inS, const __nv_bfloat16* wS,
                                        int mw, int nw, int lane, float acc[2][8][4])
{
    #pragma unroll
    for (int mt = 0; mt < 2; mt++)
        #pragma unroll
        for (int nt = 0; nt < 8; nt++)
            #pragma unroll
            for (int i = 0; i < 4; i++) acc[mt][nt][i] = 0.f;

    int l16 = lane & 15, lh = lane >> 4;
    #pragma unroll
    for (int kk = 0; kk < 8; kk++) {
        int ks = kk * 16;
        uint32_t a[2][4];
        #pragma unroll
        for (int mt = 0; mt < 2; mt++) {
            const __nv_bfloat16* p = inS + (mw * 32 + mt * 16 + l16) * LDS_ROW + ks + 8 * lh;
            ldm_x4(smem_u32(p), a[mt][0], a[mt][1], a[mt][2], a[mt][3]);
        }
        uint32_t b[8][2];
        #pragma unroll
        for (int np = 0; np < 4; np++) {
            const __nv_bfloat16* p = wS + (ks + l16) * LDS_ROW + nw * 64 + np * 16 + 8 * lh;
            uint32_t r0, r1, r2, r3;
            ldm_x4_t(smem_u32(p), r0, r1, r2, r3);
            b[np * 2][0] = r0; b[np * 2][1] = r1;
            b[np * 2 + 1][0] = r2; b[np * 2 + 1][1] = r3;
        }
        #pragma unroll
        for (int mt = 0; mt < 2; mt++)
            #pragma unroll
            for (int nt = 0; nt < 8; nt++)
                mma_bf16(acc[mt][nt], a[mt][0], a[mt][1], a[mt][2], a[mt][3],
                         b[nt][0], b[nt][1]);
    }
}

__device__ __forceinline__ void epi_relu_store(float acc[2][8][4], const float* biasS,
                                               __nv_bfloat16* outS, int mw, int nw, int lane)
{
    int qrow = lane >> 2, qcol = (lane & 3) * 2;
    #pragma unroll
    for (int mt = 0; mt < 2; mt++) {
        int r = mw * 32 + mt * 16 + qrow;
        #pragma unroll
        for (int nt = 0; nt < 8; nt++) {
            int c = nw * 64 + nt * 8 + qcol;
            float b0 = biasS[c], b1 = biasS[c + 1];
            float v0 = fmaxf(acc[mt][nt][0] + b0, 0.f);
            float v1 = fmaxf(acc[mt][nt][1] + b1, 0.f);
            float v2 = fmaxf(acc[mt][nt][2] + b0, 0.f);
            float v3 = fmaxf(acc[mt][nt][3] + b1, 0.f);
            *(__nv_bfloat162*)(outS + r * LDS_ROW + c)       = __floats2bfloat162_rn(v0, v1);
            *(__nv_bfloat162*)(outS + (r + 8) * LDS_ROW + c) = __floats2bfloat162_rn(v2, v3);
        }
    }
}

__device__ __forceinline__ void load_weights(const __nv_bfloat16* __restrict__ g,
                                             __nv_bfloat16* wS, int tid)
{
    #pragma unroll
    for (int it = 0; it < 8; it++) {
        int e = tid + it * 256;        // 0..2047, 16B each
        int k = e >> 4, nq = e & 15;
        *(uint4*)(wS + k * LDS_ROW + nq * 8) = ((const uint4*)g)[e];
    }
}

// ------------------------- fused main kernel -------------------------
__global__ void __launch_bounds__(256, 2)
umnn_main(const float* __restrict__ x)
{
    extern __shared__ __align__(16) __nv_bfloat16 sm[];
    __nv_bfloat16* As1 = sm;
    __nv_bfloat16* As2 = sm + 128 * LDS_ROW;
    __nv_bfloat16* Ws  = sm + 2 * 128 * LDS_ROW;
    __shared__ float xs[2][128];
    __shared__ float Gs[128];
    __shared__ float bc2[128], bc3[128], bc4[128];
    __shared__ float rowT[128];
    __shared__ int   rowb[128];
    __shared__ unsigned char rowsel[128];

    int tid = threadIdx.x;
    int lane = tid & 31, warp = tid >> 5;
    int mw = warp & 3, nw = warp >> 2;
    int r0 = blockIdx.x * CTA_ROWS;
    int b0 = r0 / T_STEPS;
    int b1 = (r0 + CTA_ROWS - 1) / T_STEPS;

    if (tid < 128) {
        int r = r0 + tid;
        int b = r / T_STEPS;
        int t = r - b * T_STEPS;
        rowb[tid] = b;
        rowsel[tid] = (unsigned char)(b != b0);
        rowT[tid] = ((float)t + 0.5f) * (1.0f / T_STEPS);
        Gs[tid] = 0.f;
        bc2[tid] = g_c2p[tid];
        bc3[tid] = g_c3p[tid];
        bc4[tid] = g_c4p[tid];
        xs[0][tid] = x[b0 * D_SZ + tid];
    } else {
        xs[1][tid - 128] = x[b1 * D_SZ + (tid - 128)];
    }
    __syncthreads();

    // Build A1 = relu(t*P + Q) as bf16, and stage U2 weights.
    #pragma unroll
    for (int it = 0; it < 16; it++) {
        int e = tid + it * 256;        // 0..4095: (row, float4-col)
        int lr = e >> 5;
        int kq = e & 31;
        int b = rowb[lr];
        float tv = rowT[lr];
        float4 p = *(const float4*)(g_P + b * HP + kq * 4);
        float4 q = *(const float4*)(g_Q + b * HP + kq * 4);
        float v0 = fmaxf(tv * p.x + q.x, 0.f);
        float v1 = fmaxf(tv * p.y + q.y, 0.f);
        float v2 = fmaxf(tv * p.z + q.z, 0.f);
        float v3 = fmaxf(tv * p.w + q.w, 0.f);
        __nv_bfloat162* dst = (__nv_bfloat162*)(As1 + lr * LDS_ROW + kq * 4);
        dst[0] = __floats2bfloat162_rn(v0, v1);
        dst[1] = __floats2bfloat162_rn(v2, v3);
    }
    load_weights(g_U2b, Ws, tid);
    __syncthreads();

    float acc[2][8][4];

    // Layer 2: A2 = relu(A1 @ U2 + c2)
    gemm128(As1, Ws, mw, nw, lane, acc);
    epi_relu_store(acc, bc2, As2, mw, nw, lane);
    __syncthreads();
    load_weights(g_U3b, Ws, tid);
    __syncthreads();

    // Layer 3: A3 = relu(A2 @ U3 + c3)
    gemm128(As2, Ws, mw, nw, lane, acc);
    epi_relu_store(acc, bc3, As1, mw, nw, lane);
    __syncthreads();
    load_weights(g_U4b, Ws, tid);
    __syncthreads();

    // Layer 4: f = elu(A3 @ U4 + c4) + 1 ; G_row += f . x_b
    gemm128(As1, Ws, mw, nw, lane, acc);
    {
        int qrow = lane >> 2, qcol = (lane & 3) * 2;
        #pragma unroll
        for (int mt = 0; mt < 2; mt++) {
            int rA = mw * 32 + mt * 16 + qrow;
            int rB = rA + 8;
            int selA = rowsel[rA], selB = rowsel[rB];
            float sA = 0.f, sB = 0.f;
            #pragma unroll
            for (int nt = 0; nt < 8; nt++) {
                int c = nw * 64 + nt * 8 + qcol;
                float bv0 = bc4[c], bv1 = bc4[c + 1];
                float p0 = acc[mt][nt][0] + bv0, p1 = acc[mt][nt][1] + bv1;
                float p2 = acc[mt][nt][2] + bv0, p3 = acc[mt][nt][3] + bv1;
                float f0 = p0 > 0.f ? p0 + 1.f : __expf(p0);
                float f1 = p1 > 0.f ? p1 + 1.f : __expf(p1);
                float f2 = p2 > 0.f ? p2 + 1.f : __expf(p2);
                float f3 = p3 > 0.f ? p3 + 1.f : __expf(p3);
                sA += f0 * xs[selA][c] + f1 * xs[selA][c + 1];
                sB += f2 * xs[selB][c] + f3 * xs[selB][c + 1];
            }
            sA += __shfl_xor_sync(0xffffffff, sA, 1);
            sA += __shfl_xor_sync(0xffffffff, sA, 2);
            sB += __shfl_xor_sync(0xffffffff, sB, 1);
            sB += __shfl_xor_sync(0xffffffff, sB, 2);
            if ((lane & 3) == 0) {
                atomicAdd(&Gs[rA], sA);
                atomicAdd(&Gs[rB], sB);
            }
        }
    }
    __syncthreads();
    if (tid < 128) atomicAdd(&g_F[rowb[tid]], Gs[tid]);
}

// ------------------------- finish: sigmoid(F / T) -------------------------
__global__ void finish_kernel(float* __restrict__ out)
{
    int i = blockIdx.x * blockDim.x + threadIdx.x;
    if (i < B_SZ) {
        float F = g_F[i] * (1.0f / T_STEPS);
        out[i] = 1.0f / (1.0f + expf(-F));
    }
}

// ------------------------- launch -------------------------
extern "C" void kernel_launch(void* const* d_in, const int* in_sizes, int n_in,
                              void* d_out, int out_size)
{
    (void)in_sizes; (void)n_in; (void)out_size;
    const float* x  = (const float*)d_in[0];
    const float* W1 = (const float*)d_in[1];
    const float* b1 = (const float*)d_in[2];
    const float* W2 = (const float*)d_in[3];
    const float* b2 = (const float*)d_in[4];
    const float* W3 = (const float*)d_in[5];
    const float* b3 = (const float*)d_in[6];
    const float* U1 = (const float*)d_in[7];
    const float* c1 = (const float*)d_in[8];
    const float* U2 = (const float*)d_in[9];
    const float* c2 = (const float*)d_in[10];
    const float* U3 = (const float*)d_in[11];
    const float* c3 = (const float*)d_in[12];
    const float* U4 = (const float*)d_in[13];
    const float* c4 = (const float*)d_in[14];
    float* out = (float*)d_out;

    float *ph1, *ph2, *ph, *pP, *pQ;
    cudaGetSymbolAddress((void**)&ph1, g_h1);
    cudaGetSymbolAddress((void**)&ph2, g_h2);
    cudaGetSymbolAddress((void**)&ph,  g_h);
    cudaGetSymbolAddress((void**)&pP,  g_P);
    cudaGetSymbolAddress((void**)&pQ,  g_Q);

    cudaFuncSetAttribute(umnn_main, cudaFuncAttributeMaxDynamicSharedMemorySize, SMEM_MAIN);

    // weight packing (bf16, padded) + bias padding + zero F accumulator
    pack_kernel<<<dim3(64, 4), 256>>>(U2, U3, U4, c2, c3, c4);

    // embedding MLP: h = relu(relu(relu(x W1+b1) W2+b2) W3+b3)
    gemm_kernel<<<dim3(4, 32), 256>>>(x,   D_SZ, W1, H1,   b1, ph1, H1,   B_SZ, H1,   D_SZ, H1,   1);
    gemm_kernel<<<dim3(4, 32), 256>>>(ph1, H1,   W2, H1,   b2, ph2, H1,   B_SZ, H1,   H1,   H1,   1);
    gemm_kernel<<<dim3(1, 32), 256>>>(ph2, H1,   W3, C_SZ, b3, ph,  C_SZ, B_SZ, C_SZ, H1,   C_SZ, 1);

    // P = x @ U1[:128,:] (no bias/act), Q = h @ U1[128:,:] + c1 (no act); both zero-padded to 128
    gemm_kernel<<<dim3(2, 32), 256>>>(x,  D_SZ, U1,               HU, nullptr, pP, HP, B_SZ, HU, D_SZ, HP, 0);
    gemm_kernel<<<dim3(2, 32), 256>>>(ph, C_SZ, U1 + D_SZ * HU,   HU, c1,      pQ, HP, B_SZ, HU, C_SZ, HP, 0);

    // fused UMNN chain + quadrature reduction
    umnn_main<<<NUM_CTAS, 256, SMEM_MAIN>>>(x);

    // out = sigmoid(F / 300)
    finish_kernel<<<(B_SZ + 255) / 256, 256>>>(out);
}